// round 7
// baseline (speedup 1.0000x reference)
#include <cuda_runtime.h>

#define Bsz 64
#define Ssz 512
#define Hsz 512
#define Isz 512
#define KT  32

typedef unsigned long long u64;

// Scratch (allocation-free rule: __device__ globals)
__device__ float g_xw[134217728];         // [d][s][g][h][b] : 512MB
__device__ float g_h[2][2][Hsz][Bsz];     // [dir][buf][h(k)][b]
__device__ u64   g_U2[2][Hsz][Hsz][4];    // [dir][k][h][g] = {U,U} dup pairs, 16MB
__device__ unsigned g_bar[64];            // barrier counters: [0]=fwd, [32]=bwd

__device__ __forceinline__ u64 packf2(float x, float y) {
    u64 r; asm("mov.b64 %0, {%1,%2};" : "=l"(r) : "f"(x), "f"(y)); return r;
}
__device__ __forceinline__ void unpack2(u64 v, float& x, float& y) {
    asm("mov.b64 {%0,%1}, %2;" : "=f"(x), "=f"(y) : "l"(v));
}
__device__ __forceinline__ void fma2(u64& d, u64 a, u64 b) {
    asm("fma.rn.f32x2 %0, %1, %2, %0;" : "+l"(d) : "l"(a), "l"(b));
}
__device__ __forceinline__ float sigm(float x) {
    float e; asm("ex2.approx.f32 %0, %1;" : "=f"(e) : "f"(x * -1.4426950408889634f));
    float r; asm("rcp.approx.f32 %0, %1;" : "=f"(r) : "f"(1.0f + e));
    return r;
}
__device__ __forceinline__ float tanh_(float x) {
    float e; asm("ex2.approx.f32 %0, %1;" : "=f"(e) : "f"(x * 2.8853900817779268f));
    float r; asm("rcp.approx.f32 %0, %1;" : "=f"(r) : "f"(1.0f + e));
    return 1.0f - 2.0f * r;
}
__device__ __forceinline__ void cpa16(unsigned dst, const void* src) {
    asm volatile("cp.async.ca.shared.global [%0], [%1], 16;" :: "r"(dst), "l"(src));
}
__device__ __forceinline__ void cpa_commit() {
    asm volatile("cp.async.commit_group;");
}
template<int N> __device__ __forceinline__ void cpa_wait() {
    asm volatile("cp.async.wait_group %0;" :: "n"(N));
}

// ---------------------------------------------------------------------------
__global__ void k_init() {
    int i = blockIdx.x * 256 + threadIdx.x;
    float* ph = &g_h[0][0][0][0];
    if (i < 2 * 2 * Hsz * Bsz) ph[i] = 0.0f;
    if (i < 64) g_bar[i] = 0u;
}

// Build g_U2[d][k][h][g] = {U[d][g][k][h], same}.
__global__ void k_u2(const float* __restrict__ Uf, const float* __restrict__ Ub) {
    int i = blockIdx.x * 256 + threadIdx.x;       // over 2*512*512 (d,k,h)
    int d = i >> 18;
    int k = (i >> 9) & 511;
    int h = i & 511;
    const float* U = d ? Ub : Uf;
    #pragma unroll
    for (int g = 0; g < 4; g++) {
        float u = U[(size_t)g * (Hsz * Hsz) + (size_t)k * Hsz + h];
        g_U2[d][k][h][g] = packf2(u, u);
    }
}

// ---------------------------------------------------------------------------
// Input projection: xw[d][s][g][h][b] = sum_i x[b][s][i] * W_d[g][i][h] + b_d[g][h]
__global__ __launch_bounds__(256) void k_xw(
    const float* __restrict__ x,
    const float* __restrict__ Wf, const float* __restrict__ Wb,
    const float* __restrict__ bf, const float* __restrict__ bb)
{
    __shared__ float As[32][66];   // As[k][row(b)]
    __shared__ float Bs[32][68];   // Bs[k][col(h)]

    const int tid = threadIdx.x;
    const int s = blockIdx.y;
    const int ct = blockIdx.x;             // 0..63
    const int d = ct >> 5;
    const int g = (ct >> 3) & 3;
    const int h0 = (ct & 7) * 64;

    const float* W = (d ? Wb : Wf) + (size_t)g * Hsz * Isz + h0;
    const float* bias = (d ? bb : bf) + g * Hsz + h0;

    const int ra = tid >> 3, k4 = tid & 7;     // A staging
    const int c4 = tid & 15, kb = tid >> 4;    // B staging
    const float* xg = x + ((size_t)ra * Ssz + s) * Isz + k4 * 4;
    const size_t xrow2 = (size_t)32 * Ssz * Isz;

    const int l = tid & 31, w = tid >> 5;

    u64 acc[2][4] = {};

    float4 rA0 = *(const float4*)(xg);
    float4 rA1 = *(const float4*)(xg + xrow2);
    float4 rB0 = *(const float4*)(W + (size_t)kb * Hsz + c4 * 4);
    float4 rB1 = *(const float4*)(W + (size_t)(kb + 16) * Hsz + c4 * 4);

    for (int t = 0; t < 16; t++) {
        {
            int kk = k4 * 4;
            As[kk + 0][ra] = rA0.x; As[kk + 1][ra] = rA0.y;
            As[kk + 2][ra] = rA0.z; As[kk + 3][ra] = rA0.w;
            As[kk + 0][ra + 32] = rA1.x; As[kk + 1][ra + 32] = rA1.y;
            As[kk + 2][ra + 32] = rA1.z; As[kk + 3][ra + 32] = rA1.w;
            *(float4*)&Bs[kb][c4 * 4] = rB0;
            *(float4*)&Bs[kb + 16][c4 * 4] = rB1;
        }
        __syncthreads();
        if (t < 15) {
            int k0 = (t + 1) * 32;
            rA0 = *(const float4*)(xg + k0);
            rA1 = *(const float4*)(xg + xrow2 + k0);
            rB0 = *(const float4*)(W + (size_t)(k0 + kb) * Hsz + c4 * 4);
            rB1 = *(const float4*)(W + (size_t)(k0 + kb + 16) * Hsz + c4 * 4);
        }
        #pragma unroll
        for (int kk = 0; kk < 32; kk++) {
            float2 a = *(const float2*)&As[kk][2 * l];
            u64 a0 = packf2(a.x, a.x);
            u64 a1 = packf2(a.y, a.y);
            ulonglong2 b01 = *(const ulonglong2*)&Bs[kk][8 * w];
            ulonglong2 b23 = *(const ulonglong2*)&Bs[kk][8 * w + 4];
            fma2(acc[0][0], a0, b01.x); fma2(acc[0][1], a0, b01.y);
            fma2(acc[0][2], a0, b23.x); fma2(acc[0][3], a0, b23.y);
            fma2(acc[1][0], a1, b01.x); fma2(acc[1][1], a1, b01.y);
            fma2(acc[1][2], a1, b23.x); fma2(acc[1][3], a1, b23.y);
        }
        __syncthreads();
    }

    size_t gb = (((size_t)d * Ssz + s) * 4 + g) * (size_t)Hsz * Bsz;
    #pragma unroll
    for (int j = 0; j < 4; j++) {
        float2 bb2 = *(const float2*)&bias[8 * w + 2 * j];
        float p0, p1, q0, q1;
        unpack2(acc[0][j], p0, p1);
        unpack2(acc[1][j], q0, q1);
        int hc = h0 + 8 * w + 2 * j;
        *(float2*)&g_xw[gb + (size_t)hc * Bsz + 2 * l] =
            make_float2(p0 + bb2.x, q0 + bb2.x);
        *(float2*)&g_xw[gb + (size_t)(hc + 1) * Bsz + 2 * l] =
            make_float2(p1 + bb2.y, q1 + bb2.y);
    }
}

// ---------------------------------------------------------------------------
// Persistent recurrence kernel. Grid 128 (d = bx>>6, 8-h slab), 256 threads,
// 1 block/SM. U slab in smem once; h tiles streamed per step via a 4-stage
// cp.async ring; grid-sync-style barrier (tid0 fence+arrive / fence+spin).
// Dynamic smem: As[4][32][64] f32 (32KB) | Bs[512][8][4] u64 (128KB) | ob (2KB)
#define SM_AS   0
#define SM_BS   32768
#define SM_OB   (32768 + 131072)
#define SM_REC  (SM_OB + 2048)

__global__ __launch_bounds__(256, 1) void k_rec(float* __restrict__ out)
{
    extern __shared__ char smraw[];
    float* As  = (float*)(smraw + SM_AS);    // [4][32][64]
    u64*   Bs  = (u64*)  (smraw + SM_BS);    // [k][hl][g] = [512][8][4]
    float* ob  = (float*)(smraw + SM_OB);    // [64][8]

    const int tid = threadIdx.x;
    const int d = blockIdx.x >> 6;
    const int hh0 = (blockIdx.x & 63) * 8;

    // ---- load U slab once
    {
        const u64* src = &g_U2[d][0][0][0];
        for (int i = tid; i < 16384; i += 256)
            Bs[i] = src[((size_t)(i >> 5)) * 2048 + hh0 * 4 + (i & 31)];
    }

    // compute indices
    const int l = tid & 31, w = tid >> 5;
    const int r0 = 16 * (w & 3) + 2 * (l & 7);
    const int hl = 4 * (w >> 2) + (l >> 3);
    const int h = hh0 + hl;

    // A staging indices (cp.async): thread -> (k-row kA, 8-float seg segA)
    const int kA = tid >> 3, segA = tid & 7;
    unsigned asp;   // smem dst base (stage 0) for this thread
    {
        unsigned a32 = (unsigned)__cvta_generic_to_shared(As);
        asp = a32 + (unsigned)((kA * 64 + segA * 8) * 4);
    }

    volatile unsigned* barp = &g_bar[d * 32];
    unsigned* barw = (unsigned*)&g_bar[d * 32];

    const float* xwd = &g_xw[0] + (size_t)d * Ssz * 4 * Hsz * Bsz
                     + (size_t)h * Bsz + r0;
    const u64* Bp = Bs + hl * 4;

    float c0 = 0.0f, c1 = 0.0f;
    __syncthreads();   // U slab visible

    #pragma unroll 1
    for (int t = 0; t < Ssz; t++) {
        const int s = d ? (Ssz - 1 - t) : t;
        const int buf = t & 1;
        const float* hp = &g_h[d][buf][0][0] + (size_t)kA * Bsz + segA * 8;

        // seed acc with xw (issued before barrier wait -> overlaps spin)
        u64 acc[4];
        {
            const float* xwp = xwd + (size_t)s * 4 * Hsz * Bsz;
            #pragma unroll
            for (int g = 0; g < 4; g++)
                acc[g] = *(const u64*)(xwp + (size_t)g * Hsz * Bsz);
        }

        // wait for all blocks of this direction to finish step t-1
        if (t > 0) {
            if (tid == 0) {
                while (*barp < (unsigned)(64 * t)) { }
                __threadfence();   // acquire
            }
            __syncthreads();
        }

        // prologue: issue h tiles 0..2 into ring stages 0..2
        #pragma unroll
        for (int pt = 0; pt < 3; pt++) {
            cpa16(asp + pt * 8192u, hp + pt * (KT * Bsz));
            cpa16(asp + pt * 8192u + 16u, hp + pt * (KT * Bsz) + 4);
            cpa_commit();
        }

        #pragma unroll 1
        for (int tt = 0; tt < 16; tt++) {
            if (tt < 14) cpa_wait<2>();
            else if (tt == 14) cpa_wait<1>();
            else cpa_wait<0>();
            __syncthreads();

            if (tt < 13) {
                int it = tt + 3;
                cpa16(asp + (it & 3) * 8192u, hp + it * (KT * Bsz));
                cpa16(asp + (it & 3) * 8192u + 16u, hp + it * (KT * Bsz) + 4);
                cpa_commit();
            }

            const float* Asb = As + (tt & 3) * (32 * 64);
            const u64* Bt = Bp + (size_t)tt * KT * 32;
            #pragma unroll
            for (int kk = 0; kk < KT; kk++) {
                u64 a2 = *(const u64*)&Asb[kk * 64 + r0];
                ulonglong2 b01 = *(const ulonglong2*)(Bt + (size_t)kk * 32);
                ulonglong2 b23 = *(const ulonglong2*)(Bt + (size_t)kk * 32 + 2);
                fma2(acc[0], a2, b01.x);
                fma2(acc[1], a2, b01.y);
                fma2(acc[2], a2, b23.x);
                fma2(acc[3], a2, b23.y);
            }
        }

        // Pointwise LSTM cell (gate order: f, g, i, o); c lives in registers.
        float f0, f1, gg0, gg1, i0, i1, o0, o1;
        unpack2(acc[0], f0, f1);
        unpack2(acc[1], gg0, gg1);
        unpack2(acc[2], i0, i1);
        unpack2(acc[3], o0, o1);

        float cn0 = c0 * sigm(f0) + tanh_(gg0) * sigm(i0);
        float cn1 = c1 * sigm(f1) + tanh_(gg1) * sigm(i1);
        c0 = cn0; c1 = cn1;

        float hv0 = sigm(o0) * tanh_(cn0);
        float hv1 = sigm(o1) * tanh_(cn1);

        // publish h_new for next step; stage out tile in smem
        *(float2*)&g_h[d][buf ^ 1][h][r0] = make_float2(hv0, hv1);
        ob[r0 * 8 + hl] = hv0;
        ob[(r0 + 1) * 8 + hl] = hv1;

        __syncthreads();                      // all stores executed, all reads done
        if (tid == 0) {
            __threadfence();                  // release (grid.sync pattern)
            atomicAdd(barw, 1u);
        }

        // coalesced out write: out[s][b][d*512 + hh0 + 0..7] (overlaps next spin)
        if (tid < 128) {
            int b = tid >> 1, hseg = (tid & 1) * 4;
            float4 v = *(float4*)&ob[b * 8 + hseg];
            *(float4*)&out[(size_t)s * (Bsz * 2 * Hsz) + (size_t)b * (2 * Hsz)
                           + d * Hsz + hh0 + hseg] = v;
        }
        // ob reuse is safe: next step's ob writes happen only after the next
        // barrier release + full compute, and the LDS into v completed above.
    }
}

// ---------------------------------------------------------------------------
__global__ void k_gather(const unsigned char* __restrict__ mask,
                         const float* __restrict__ out,
                         float* __restrict__ hf, float* __restrict__ hb)
{
    __shared__ int sred[256];
    __shared__ int smode;
    const int b = blockIdx.x, tid = threadIdx.x;

    if (tid == 0) {
        const int* ip = (const int*)mask;
        int bytemode = 0;
        for (int j = 0; j < 8; j++) {
            unsigned int v = (unsigned int)ip[j];
            if (v > 1u) bytemode = 1;
        }
        smode = bytemode;
    }
    __syncthreads();

    int v;
    if (smode) {
        v  = mask[b * Ssz + tid] ? 1 : 0;
        v += mask[b * Ssz + 256 + tid] ? 1 : 0;
    } else {
        const int* ip = (const int*)mask;
        v  = ip[b * Ssz + tid] ? 1 : 0;
        v += ip[b * Ssz + 256 + tid] ? 1 : 0;
    }
    sred[tid] = v;
    __syncthreads();
    for (int st = 128; st > 0; st >>= 1) {
        if (tid < st) sred[tid] += sred[tid + st];
        __syncthreads();
    }
    int len = sred[0];
    int idx = len > 0 ? len - 1 : 0;

    hf[b * Hsz + tid]       = out[(size_t)idx * 65536 + b * 1024 + tid];
    hf[b * Hsz + tid + 256] = out[(size_t)idx * 65536 + b * 1024 + tid + 256];
    hb[b * Hsz + tid]       = out[(size_t)b * 1024 + 512 + tid];
    hb[b * Hsz + tid + 256] = out[(size_t)b * 1024 + 512 + tid + 256];
}

// ---------------------------------------------------------------------------
extern "C" void kernel_launch(void* const* d_in, const int* in_sizes, int n_in,
                              void* d_out, int out_size)
{
    const float* x  = (const float*)d_in[0];
    const unsigned char* mask = (const unsigned char*)d_in[1];
    const float* Uf = (const float*)d_in[2];
    const float* Wf = (const float*)d_in[3];
    const float* bf = (const float*)d_in[4];
    const float* Ub = (const float*)d_in[5];
    const float* Wb = (const float*)d_in[6];
    const float* bb = (const float*)d_in[7];

    float* out = (float*)d_out;                       // [S][B][2H]
    float* hf  = out + (size_t)Ssz * Bsz * 2 * Hsz;   // [B][H]
    float* hb  = hf + (size_t)Bsz * Hsz;              // [B][H]

    k_init<<<512, 256>>>();
    k_u2<<<2048, 256>>>(Uf, Ub);

    dim3 gx(64, 512);
    k_xw<<<gx, 256>>>(x, Wf, Wb, bf, bb);

    cudaFuncSetAttribute(k_rec, cudaFuncAttributeMaxDynamicSharedMemorySize, SM_REC);
    k_rec<<<128, 256, SM_REC>>>(out);

    k_gather<<<64, 256>>>(mask, out, hf, hb);
}

// round 8
// speedup vs baseline: 1.2187x; 1.2187x over previous
#include <cuda_runtime.h>

#define Bsz 64
#define Ssz 512
#define Hsz 512
#define Isz 512
#define KT  64

typedef unsigned long long u64;

// Scratch (allocation-free rule: __device__ globals)
__device__ float g_xw[134217728];         // [d][s][g][h][b] : 512MB
__device__ float g_h[2][2][Hsz][Bsz];     // [dir][buf][h(k)][b]
__device__ u64   g_U2[2][Hsz][Hsz][4];    // [dir][k][h][g] = {U,U} dup pairs, 16MB
__device__ unsigned g_flag[2][64];        // per-block step flags

__device__ __forceinline__ u64 packf2(float x, float y) {
    u64 r; asm("mov.b64 %0, {%1,%2};" : "=l"(r) : "f"(x), "f"(y)); return r;
}
__device__ __forceinline__ void unpack2(u64 v, float& x, float& y) {
    asm("mov.b64 {%0,%1}, %2;" : "=f"(x), "=f"(y) : "l"(v));
}
__device__ __forceinline__ void fma2(u64& d, u64 a, u64 b) {
    asm("fma.rn.f32x2 %0, %1, %2, %0;" : "+l"(d) : "l"(a), "l"(b));
}
__device__ __forceinline__ float sigm(float x) {
    float e; asm("ex2.approx.f32 %0, %1;" : "=f"(e) : "f"(x * -1.4426950408889634f));
    float r; asm("rcp.approx.f32 %0, %1;" : "=f"(r) : "f"(1.0f + e));
    return r;
}
__device__ __forceinline__ float tanh_(float x) {
    float e; asm("ex2.approx.f32 %0, %1;" : "=f"(e) : "f"(x * 2.8853900817779268f));
    float r; asm("rcp.approx.f32 %0, %1;" : "=f"(r) : "f"(1.0f + e));
    return 1.0f - 2.0f * r;
}
__device__ __forceinline__ void st_release(unsigned* p, unsigned v) {
    asm volatile("st.release.gpu.global.u32 [%0], %1;" :: "l"(p), "r"(v) : "memory");
}
__device__ __forceinline__ unsigned ld_acquire(const unsigned* p) {
    unsigned v;
    asm volatile("ld.acquire.gpu.global.u32 %0, [%1];" : "=r"(v) : "l"(p) : "memory");
    return v;
}

// ---------------------------------------------------------------------------
__global__ void k_init() {
    int i = blockIdx.x * 256 + threadIdx.x;
    float* ph = &g_h[0][0][0][0];
    if (i < 2 * 2 * Hsz * Bsz) ph[i] = 0.0f;
    if (i < 128) (&g_flag[0][0])[i] = 0u;
}

// Build g_U2[d][k][h][g] = {U[d][g][k][h], same}.
__global__ void k_u2(const float* __restrict__ Uf, const float* __restrict__ Ub) {
    int i = blockIdx.x * 256 + threadIdx.x;       // over 2*512*512 (d,k,h)
    int d = i >> 18;
    int k = (i >> 9) & 511;
    int h = i & 511;
    const float* U = d ? Ub : Uf;
    #pragma unroll
    for (int g = 0; g < 4; g++) {
        float u = U[(size_t)g * (Hsz * Hsz) + (size_t)k * Hsz + h];
        g_U2[d][k][h][g] = packf2(u, u);
    }
}

// ---------------------------------------------------------------------------
// Input projection: xw[d][s][g][h][b] = sum_i x[b][s][i] * W_d[g][i][h] + b_d[g][h]
__global__ __launch_bounds__(256) void k_xw(
    const float* __restrict__ x,
    const float* __restrict__ Wf, const float* __restrict__ Wb,
    const float* __restrict__ bf, const float* __restrict__ bb)
{
    __shared__ float As[32][66];   // As[k][row(b)]
    __shared__ float Bs[32][68];   // Bs[k][col(h)]

    const int tid = threadIdx.x;
    const int s = blockIdx.y;
    const int ct = blockIdx.x;             // 0..63
    const int d = ct >> 5;
    const int g = (ct >> 3) & 3;
    const int h0 = (ct & 7) * 64;

    const float* W = (d ? Wb : Wf) + (size_t)g * Hsz * Isz + h0;
    const float* bias = (d ? bb : bf) + g * Hsz + h0;

    const int ra = tid >> 3, k4 = tid & 7;     // A staging
    const int c4 = tid & 15, kb = tid >> 4;    // B staging
    const float* xg = x + ((size_t)ra * Ssz + s) * Isz + k4 * 4;
    const size_t xrow2 = (size_t)32 * Ssz * Isz;

    const int l = tid & 31, w = tid >> 5;

    u64 acc[2][4] = {};

    float4 rA0 = *(const float4*)(xg);
    float4 rA1 = *(const float4*)(xg + xrow2);
    float4 rB0 = *(const float4*)(W + (size_t)kb * Hsz + c4 * 4);
    float4 rB1 = *(const float4*)(W + (size_t)(kb + 16) * Hsz + c4 * 4);

    for (int t = 0; t < 16; t++) {
        {
            int kk = k4 * 4;
            As[kk + 0][ra] = rA0.x; As[kk + 1][ra] = rA0.y;
            As[kk + 2][ra] = rA0.z; As[kk + 3][ra] = rA0.w;
            As[kk + 0][ra + 32] = rA1.x; As[kk + 1][ra + 32] = rA1.y;
            As[kk + 2][ra + 32] = rA1.z; As[kk + 3][ra + 32] = rA1.w;
            *(float4*)&Bs[kb][c4 * 4] = rB0;
            *(float4*)&Bs[kb + 16][c4 * 4] = rB1;
        }
        __syncthreads();
        if (t < 15) {
            int k0 = (t + 1) * 32;
            rA0 = *(const float4*)(xg + k0);
            rA1 = *(const float4*)(xg + xrow2 + k0);
            rB0 = *(const float4*)(W + (size_t)(k0 + kb) * Hsz + c4 * 4);
            rB1 = *(const float4*)(W + (size_t)(k0 + kb + 16) * Hsz + c4 * 4);
        }
        #pragma unroll
        for (int kk = 0; kk < 32; kk++) {
            float2 a = *(const float2*)&As[kk][2 * l];
            u64 a0 = packf2(a.x, a.x);
            u64 a1 = packf2(a.y, a.y);
            ulonglong2 b01 = *(const ulonglong2*)&Bs[kk][8 * w];
            ulonglong2 b23 = *(const ulonglong2*)&Bs[kk][8 * w + 4];
            fma2(acc[0][0], a0, b01.x); fma2(acc[0][1], a0, b01.y);
            fma2(acc[0][2], a0, b23.x); fma2(acc[0][3], a0, b23.y);
            fma2(acc[1][0], a1, b01.x); fma2(acc[1][1], a1, b01.y);
            fma2(acc[1][2], a1, b23.x); fma2(acc[1][3], a1, b23.y);
        }
        __syncthreads();
    }

    size_t gb = (((size_t)d * Ssz + s) * 4 + g) * (size_t)Hsz * Bsz;
    #pragma unroll
    for (int j = 0; j < 4; j++) {
        float2 bb2 = *(const float2*)&bias[8 * w + 2 * j];
        float p0, p1, q0, q1;
        unpack2(acc[0][j], p0, p1);
        unpack2(acc[1][j], q0, q1);
        int hc = h0 + 8 * w + 2 * j;
        *(float2*)&g_xw[gb + (size_t)hc * Bsz + 2 * l] =
            make_float2(p0 + bb2.x, q0 + bb2.x);
        *(float2*)&g_xw[gb + (size_t)(hc + 1) * Bsz + 2 * l] =
            make_float2(p1 + bb2.y, q1 + bb2.y);
    }
}

// ---------------------------------------------------------------------------
// Persistent recurrence kernel. Grid 128 (d = bx>>6, 8-h slab), 256 threads,
// 1 block/SM (162KB smem). U slab in smem once. Per-step inter-block sync via
// 64 per-block release/acquire flags, polled in parallel by lanes 0..63.
// h tiles: KT=64, double-buffered smem with register prefetch (4xLDG.128/thr).
// Dynamic smem: As[2][64][64] f32 (32KB) | Bs[512][8][4] u64 (128KB) | ob (2KB)
#define SM_AS   0
#define SM_BS   32768
#define SM_OB   (32768 + 131072)
#define SM_REC  (SM_OB + 2048)

__global__ __launch_bounds__(256, 1) void k_rec(float* __restrict__ out)
{
    extern __shared__ char smraw[];
    float* As  = (float*)(smraw + SM_AS);    // [2][64][64]
    u64*   Bs  = (u64*)  (smraw + SM_BS);    // [k][hl][g] = [512][8][4]
    float* ob  = (float*)(smraw + SM_OB);    // [64][8]

    const int tid = threadIdx.x;
    const int d = blockIdx.x >> 6;
    const int blk = blockIdx.x & 63;
    const int hh0 = blk * 8;

    // ---- load U slab once
    {
        const u64* src = &g_U2[d][0][0][0];
        for (int i = tid; i < 16384; i += 256)
            Bs[i] = src[((size_t)(i >> 5)) * 2048 + hh0 * 4 + (i & 31)];
    }

    // compute indices
    const int l = tid & 31, w = tid >> 5;
    const int r0 = 16 * (w & 3) + 2 * (l & 7);
    const int hl = 4 * (w >> 2) + (l >> 3);
    const int h = hh0 + hl;

    // A staging indices: thread -> k-row (tid>>2), 16-float segment (tid&3)
    const int rowA = tid >> 2, segA = (tid & 3) * 16;

    unsigned* myflag = &g_flag[d][blk];
    const unsigned* flags = &g_flag[d][0];

    const float* xwd = &g_xw[0] + (size_t)d * Ssz * 4 * Hsz * Bsz
                     + (size_t)h * Bsz + r0;
    const u64* Bp = Bs + hl * 4;

    float c0 = 0.0f, c1 = 0.0f;
    __syncthreads();   // U slab visible

    #pragma unroll 1
    for (int t = 0; t < Ssz; t++) {
        const int s = d ? (Ssz - 1 - t) : t;
        const int buf = t & 1;
        const float* hp = &g_h[d][buf][0][0] + (size_t)rowA * Bsz + segA;

        // seed acc with xw (issued before wait -> overlaps spin)
        u64 acc[4];
        {
            const float* xwp = xwd + (size_t)s * 4 * Hsz * Bsz;
            #pragma unroll
            for (int g = 0; g < 4; g++)
                acc[g] = *(const u64*)(xwp + (size_t)g * Hsz * Bsz);
        }

        // wait: all 64 blocks of this direction finished step t-1.
        // lanes 0..63 poll one flag each (acquire), then block-wide bar.
        if (t > 0) {
            if (tid < 64) {
                while (ld_acquire(flags + tid) < (unsigned)t) { }
            }
            __syncthreads();
        }

        // prologue: tile 0 -> regs -> smem buf 0
        float4 ra0 = *(const float4*)(hp);
        float4 ra1 = *(const float4*)(hp + 4);
        float4 ra2 = *(const float4*)(hp + 8);
        float4 ra3 = *(const float4*)(hp + 12);
        *(float4*)&As[rowA * 64 + segA]      = ra0;
        *(float4*)&As[rowA * 64 + segA + 4]  = ra1;
        *(float4*)&As[rowA * 64 + segA + 8]  = ra2;
        *(float4*)&As[rowA * 64 + segA + 12] = ra3;
        __syncthreads();

        #pragma unroll 1
        for (int tt = 0; tt < 8; tt++) {
            const int sb = tt & 1;
            if (tt < 7) {
                const float* hn = hp + (size_t)(tt + 1) * (KT * Bsz);
                ra0 = *(const float4*)(hn);
                ra1 = *(const float4*)(hn + 4);
                ra2 = *(const float4*)(hn + 8);
                ra3 = *(const float4*)(hn + 12);
            }
            const float* Asb = As + sb * (KT * 64);
            const u64* Bt = Bp + (size_t)tt * KT * 32;
            #pragma unroll
            for (int kk = 0; kk < KT; kk++) {
                u64 a2 = *(const u64*)&Asb[kk * 64 + r0];
                ulonglong2 b01 = *(const ulonglong2*)(Bt + (size_t)kk * 32);
                ulonglong2 b23 = *(const ulonglong2*)(Bt + (size_t)kk * 32 + 2);
                fma2(acc[0], a2, b01.x);
                fma2(acc[1], a2, b01.y);
                fma2(acc[2], a2, b23.x);
                fma2(acc[3], a2, b23.y);
            }
            if (tt < 7) {
                const int nb = sb ^ 1;
                float* dst = As + nb * (KT * 64) + rowA * 64 + segA;
                *(float4*)(dst)      = ra0;
                *(float4*)(dst + 4)  = ra1;
                *(float4*)(dst + 8)  = ra2;
                *(float4*)(dst + 12) = ra3;
                __syncthreads();
            }
        }

        // Pointwise LSTM cell (gate order: f, g, i, o); c lives in registers.
        float f0, f1, gg0, gg1, i0, i1, o0, o1;
        unpack2(acc[0], f0, f1);
        unpack2(acc[1], gg0, gg1);
        unpack2(acc[2], i0, i1);
        unpack2(acc[3], o0, o1);

        float cn0 = c0 * sigm(f0) + tanh_(gg0) * sigm(i0);
        float cn1 = c1 * sigm(f1) + tanh_(gg1) * sigm(i1);
        c0 = cn0; c1 = cn1;

        float hv0 = sigm(o0) * tanh_(cn0);
        float hv1 = sigm(o1) * tanh_(cn1);

        // publish h_new for next step; stage out tile in smem
        *(float2*)&g_h[d][buf ^ 1][h][r0] = make_float2(hv0, hv1);
        ob[r0 * 8 + hl] = hv0;
        ob[(r0 + 1) * 8 + hl] = hv1;

        __syncthreads();                      // all stores executed, reads done
        if (tid == 0) st_release(myflag, (unsigned)(t + 1));

        // coalesced out write (overlaps next spin): out[s][b][d*512+hh0+0..7]
        if (tid < 128) {
            int b = tid >> 1, hseg = (tid & 1) * 4;
            float4 v = *(float4*)&ob[b * 8 + hseg];
            *(float4*)&out[(size_t)s * (Bsz * 2 * Hsz) + (size_t)b * (2 * Hsz)
                           + d * Hsz + hh0 + hseg] = v;
        }
    }
}

// ---------------------------------------------------------------------------
__global__ void k_gather(const unsigned char* __restrict__ mask,
                         const float* __restrict__ out,
                         float* __restrict__ hf, float* __restrict__ hb)
{
    __shared__ int sred[256];
    __shared__ int smode;
    const int b = blockIdx.x, tid = threadIdx.x;

    if (tid == 0) {
        const int* ip = (const int*)mask;
        int bytemode = 0;
        for (int j = 0; j < 8; j++) {
            unsigned int v = (unsigned int)ip[j];
            if (v > 1u) bytemode = 1;
        }
        smode = bytemode;
    }
    __syncthreads();

    int v;
    if (smode) {
        v  = mask[b * Ssz + tid] ? 1 : 0;
        v += mask[b * Ssz + 256 + tid] ? 1 : 0;
    } else {
        const int* ip = (const int*)mask;
        v  = ip[b * Ssz + tid] ? 1 : 0;
        v += ip[b * Ssz + 256 + tid] ? 1 : 0;
    }
    sred[tid] = v;
    __syncthreads();
    for (int st = 128; st > 0; st >>= 1) {
        if (tid < st) sred[tid] += sred[tid + st];
        __syncthreads();
    }
    int len = sred[0];
    int idx = len > 0 ? len - 1 : 0;

    hf[b * Hsz + tid]       = out[(size_t)idx * 65536 + b * 1024 + tid];
    hf[b * Hsz + tid + 256] = out[(size_t)idx * 65536 + b * 1024 + tid + 256];
    hb[b * Hsz + tid]       = out[(size_t)b * 1024 + 512 + tid];
    hb[b * Hsz + tid + 256] = out[(size_t)b * 1024 + 512 + tid + 256];
}

// ---------------------------------------------------------------------------
extern "C" void kernel_launch(void* const* d_in, const int* in_sizes, int n_in,
                              void* d_out, int out_size)
{
    const float* x  = (const float*)d_in[0];
    const unsigned char* mask = (const unsigned char*)d_in[1];
    const float* Uf = (const float*)d_in[2];
    const float* Wf = (const float*)d_in[3];
    const float* bf = (const float*)d_in[4];
    const float* Ub = (const float*)d_in[5];
    const float* Wb = (const float*)d_in[6];
    const float* bb = (const float*)d_in[7];

    float* out = (float*)d_out;                       // [S][B][2H]
    float* hf  = out + (size_t)Ssz * Bsz * 2 * Hsz;   // [B][H]
    float* hb  = hf + (size_t)Bsz * Hsz;              // [B][H]

    k_init<<<512, 256>>>();
    k_u2<<<2048, 256>>>(Uf, Ub);

    dim3 gx(64, 512);
    k_xw<<<gx, 256>>>(x, Wf, Wb, bf, bb);

    cudaFuncSetAttribute(k_rec, cudaFuncAttributeMaxDynamicSharedMemorySize, SM_REC);
    k_rec<<<128, 256, SM_REC>>>(out);

    k_gather<<<64, 256>>>(mask, out, hf, hb);
}

// round 9
// speedup vs baseline: 1.6536x; 1.3568x over previous
#include <cuda_runtime.h>

#define Bsz 64
#define Ssz 512
#define Hsz 512
#define Isz 512
#define KT  32

typedef unsigned long long u64;

// Scratch (allocation-free rule: __device__ globals)
__device__ float g_xw[134217728];         // [d][s][g][h][b] : 512MB
__device__ float g_h[2][2][Hsz][Bsz];     // [dir][buf][h(k)][b]
__device__ u64   g_U2[2][Hsz][Hsz][4];    // [dir][k][h][g] = {U,U} dup pairs, 16MB
__device__ unsigned g_flag[2][64];        // per-block step flags

__device__ __forceinline__ u64 packf2(float x, float y) {
    u64 r; asm("mov.b64 %0, {%1,%2};" : "=l"(r) : "f"(x), "f"(y)); return r;
}
__device__ __forceinline__ void unpack2(u64 v, float& x, float& y) {
    asm("mov.b64 {%0,%1}, %2;" : "=f"(x), "=f"(y) : "l"(v));
}
__device__ __forceinline__ void fma2(u64& d, u64 a, u64 b) {
    asm("fma.rn.f32x2 %0, %1, %2, %0;" : "+l"(d) : "l"(a), "l"(b));
}
__device__ __forceinline__ float sigm(float x) {
    float e; asm("ex2.approx.f32 %0, %1;" : "=f"(e) : "f"(x * -1.4426950408889634f));
    float r; asm("rcp.approx.f32 %0, %1;" : "=f"(r) : "f"(1.0f + e));
    return r;
}
__device__ __forceinline__ float tanh_(float x) {
    float e; asm("ex2.approx.f32 %0, %1;" : "=f"(e) : "f"(x * 2.8853900817779268f));
    float r; asm("rcp.approx.f32 %0, %1;" : "=f"(r) : "f"(1.0f + e));
    return 1.0f - 2.0f * r;
}
__device__ __forceinline__ void st_release(unsigned* p, unsigned v) {
    asm volatile("st.release.gpu.global.u32 [%0], %1;" :: "l"(p), "r"(v) : "memory");
}
__device__ __forceinline__ unsigned ld_acquire(const unsigned* p) {
    unsigned v;
    asm volatile("ld.acquire.gpu.global.u32 %0, [%1];" : "=r"(v) : "l"(p) : "memory");
    return v;
}

// ---------------------------------------------------------------------------
__global__ void k_init() {
    int i = blockIdx.x * 256 + threadIdx.x;
    float* ph = &g_h[0][0][0][0];
    if (i < 2 * 2 * Hsz * Bsz) ph[i] = 0.0f;
    if (i < 128) (&g_flag[0][0])[i] = 0u;
}

// Build g_U2[d][k][h][g] = {U[d][g][k][h], same}.
__global__ void k_u2(const float* __restrict__ Uf, const float* __restrict__ Ub) {
    int i = blockIdx.x * 256 + threadIdx.x;       // over 2*512*512 (d,k,h)
    int d = i >> 18;
    int k = (i >> 9) & 511;
    int h = i & 511;
    const float* U = d ? Ub : Uf;
    #pragma unroll
    for (int g = 0; g < 4; g++) {
        float u = U[(size_t)g * (Hsz * Hsz) + (size_t)k * Hsz + h];
        g_U2[d][k][h][g] = packf2(u, u);
    }
}

// ---------------------------------------------------------------------------
// Input projection: xw[d][s][g][h][b] = sum_i x[b][s][i] * W_d[g][i][h] + b_d[g][h]
__global__ __launch_bounds__(256) void k_xw(
    const float* __restrict__ x,
    const float* __restrict__ Wf, const float* __restrict__ Wb,
    const float* __restrict__ bf, const float* __restrict__ bb)
{
    __shared__ float As[32][66];   // As[k][row(b)]
    __shared__ float Bs[32][68];   // Bs[k][col(h)]

    const int tid = threadIdx.x;
    const int s = blockIdx.y;
    const int ct = blockIdx.x;             // 0..63
    const int d = ct >> 5;
    const int g = (ct >> 3) & 3;
    const int h0 = (ct & 7) * 64;

    const float* W = (d ? Wb : Wf) + (size_t)g * Hsz * Isz + h0;
    const float* bias = (d ? bb : bf) + g * Hsz + h0;

    const int ra = tid >> 3, k4 = tid & 7;     // A staging
    const int c4 = tid & 15, kb = tid >> 4;    // B staging
    const float* xg = x + ((size_t)ra * Ssz + s) * Isz + k4 * 4;
    const size_t xrow2 = (size_t)32 * Ssz * Isz;

    const int l = tid & 31, w = tid >> 5;

    u64 acc[2][4] = {};

    float4 rA0 = *(const float4*)(xg);
    float4 rA1 = *(const float4*)(xg + xrow2);
    float4 rB0 = *(const float4*)(W + (size_t)kb * Hsz + c4 * 4);
    float4 rB1 = *(const float4*)(W + (size_t)(kb + 16) * Hsz + c4 * 4);

    for (int t = 0; t < 16; t++) {
        {
            int kk = k4 * 4;
            As[kk + 0][ra] = rA0.x; As[kk + 1][ra] = rA0.y;
            As[kk + 2][ra] = rA0.z; As[kk + 3][ra] = rA0.w;
            As[kk + 0][ra + 32] = rA1.x; As[kk + 1][ra + 32] = rA1.y;
            As[kk + 2][ra + 32] = rA1.z; As[kk + 3][ra + 32] = rA1.w;
            *(float4*)&Bs[kb][c4 * 4] = rB0;
            *(float4*)&Bs[kb + 16][c4 * 4] = rB1;
        }
        __syncthreads();
        if (t < 15) {
            int k0 = (t + 1) * 32;
            rA0 = *(const float4*)(xg + k0);
            rA1 = *(const float4*)(xg + xrow2 + k0);
            rB0 = *(const float4*)(W + (size_t)(k0 + kb) * Hsz + c4 * 4);
            rB1 = *(const float4*)(W + (size_t)(k0 + kb + 16) * Hsz + c4 * 4);
        }
        #pragma unroll
        for (int kk = 0; kk < 32; kk++) {
            float2 a = *(const float2*)&As[kk][2 * l];
            u64 a0 = packf2(a.x, a.x);
            u64 a1 = packf2(a.y, a.y);
            ulonglong2 b01 = *(const ulonglong2*)&Bs[kk][8 * w];
            ulonglong2 b23 = *(const ulonglong2*)&Bs[kk][8 * w + 4];
            fma2(acc[0][0], a0, b01.x); fma2(acc[0][1], a0, b01.y);
            fma2(acc[0][2], a0, b23.x); fma2(acc[0][3], a0, b23.y);
            fma2(acc[1][0], a1, b01.x); fma2(acc[1][1], a1, b01.y);
            fma2(acc[1][2], a1, b23.x); fma2(acc[1][3], a1, b23.y);
        }
        __syncthreads();
    }

    size_t gb = (((size_t)d * Ssz + s) * 4 + g) * (size_t)Hsz * Bsz;
    #pragma unroll
    for (int j = 0; j < 4; j++) {
        float2 bb2 = *(const float2*)&bias[8 * w + 2 * j];
        float p0, p1, q0, q1;
        unpack2(acc[0][j], p0, p1);
        unpack2(acc[1][j], q0, q1);
        int hc = h0 + 8 * w + 2 * j;
        *(float2*)&g_xw[gb + (size_t)hc * Bsz + 2 * l] =
            make_float2(p0 + bb2.x, q0 + bb2.x);
        *(float2*)&g_xw[gb + (size_t)(hc + 1) * Bsz + 2 * l] =
            make_float2(p1 + bb2.y, q1 + bb2.y);
    }
}

// ---------------------------------------------------------------------------
// Persistent recurrence kernel — round-6 structure, flag barrier only change.
// Grid 128 (d = bx>>6, 8-h slab), 256 threads, 1 block/SM. U slab in smem once.
// Dynamic smem: As[2][32][64] f32 (16KB) | Bs[512][8][4] u64 (128KB) | ob (2KB)
#define SM_AS   0
#define SM_BS   16384
#define SM_OB   (16384 + 131072)
#define SM_REC  (SM_OB + 2048)

__global__ __launch_bounds__(256, 1) void k_rec(float* __restrict__ out)
{
    extern __shared__ char smraw[];
    float* As  = (float*)(smraw + SM_AS);    // [2][32][64]
    u64*   Bs  = (u64*)  (smraw + SM_BS);    // [k][hl][g] = [512][8][4]
    float* ob  = (float*)(smraw + SM_OB);    // [64][8]

    const int tid = threadIdx.x;
    const int d = blockIdx.x >> 6;
    const int blk = blockIdx.x & 63;
    const int hh0 = blk * 8;

    // ---- load U slab once
    {
        const u64* src = &g_U2[d][0][0][0];
        for (int i = tid; i < 16384; i += 256)
            Bs[i] = src[((size_t)(i >> 5)) * 2048 + hh0 * 4 + (i & 31)];
    }

    // compute indices
    const int l = tid & 31, w = tid >> 5;
    const int r0 = 16 * (w & 3) + 2 * (l & 7);
    const int hl = 4 * (w >> 2) + (l >> 3);
    const int h = hh0 + hl;

    // staging indices for A (h_prev tile)
    const int kA = tid >> 3, segA = tid & 7;

    unsigned* myflag = &g_flag[d][blk];
    const unsigned* flags = &g_flag[d][0];

    const float* xwd = &g_xw[0] + (size_t)d * Ssz * 4 * Hsz * Bsz
                     + (size_t)h * Bsz + r0;
    const u64* Bp = Bs + hl * 4;

    float c0 = 0.0f, c1 = 0.0f;
    __syncthreads();   // U slab visible

    #pragma unroll 1
    for (int t = 0; t < Ssz; t++) {
        const int s = d ? (Ssz - 1 - t) : t;
        const int buf = t & 1;
        const float* hp = &g_h[d][buf][0][0];

        // seed acc with xw (issued before wait -> overlaps spin)
        u64 acc[4];
        {
            const float* xwp = xwd + (size_t)s * 4 * Hsz * Bsz;
            #pragma unroll
            for (int g = 0; g < 4; g++)
                acc[g] = *(const u64*)(xwp + (size_t)g * Hsz * Bsz);
        }

        // wait: all 64 blocks of this direction finished step t-1.
        if (t > 0) {
            if (tid < 64) {
                while (ld_acquire(flags + tid) < (unsigned)t) { }
            }
            __syncthreads();
        }

        // prologue: A tile 0
        float4 a0 = *(const float4*)(hp + (size_t)kA * Bsz + segA * 8);
        float4 a1 = *(const float4*)(hp + (size_t)kA * Bsz + segA * 8 + 4);
        *(float4*)&As[(0 * 32 + kA) * 64 + segA * 8] = a0;
        *(float4*)&As[(0 * 32 + kA) * 64 + segA * 8 + 4] = a1;
        __syncthreads();

        for (int tt = 0; tt < 16; tt++) {
            const int sb = tt & 1;
            if (tt < 15) {
                int k0 = (tt + 1) * KT;
                a0 = *(const float4*)(hp + (size_t)(k0 + kA) * Bsz + segA * 8);
                a1 = *(const float4*)(hp + (size_t)(k0 + kA) * Bsz + segA * 8 + 4);
            }
            const float* Asb = As + sb * (32 * 64);
            const u64* Bt = Bp + (size_t)tt * KT * 32;
            #pragma unroll
            for (int kk = 0; kk < KT; kk++) {
                u64 a2 = *(const u64*)&Asb[kk * 64 + r0];
                ulonglong2 b01 = *(const ulonglong2*)(Bt + (size_t)kk * 32);
                ulonglong2 b23 = *(const ulonglong2*)(Bt + (size_t)kk * 32 + 2);
                fma2(acc[0], a2, b01.x);
                fma2(acc[1], a2, b01.y);
                fma2(acc[2], a2, b23.x);
                fma2(acc[3], a2, b23.y);
            }
            if (tt < 15) {
                const int nb = sb ^ 1;
                *(float4*)&As[(nb * 32 + kA) * 64 + segA * 8] = a0;
                *(float4*)&As[(nb * 32 + kA) * 64 + segA * 8 + 4] = a1;
                __syncthreads();
            }
        }

        // Pointwise LSTM cell (gate order: f, g, i, o); c lives in registers.
        float f0, f1, gg0, gg1, i0, i1, o0, o1;
        unpack2(acc[0], f0, f1);
        unpack2(acc[1], gg0, gg1);
        unpack2(acc[2], i0, i1);
        unpack2(acc[3], o0, o1);

        float cn0 = c0 * sigm(f0) + tanh_(gg0) * sigm(i0);
        float cn1 = c1 * sigm(f1) + tanh_(gg1) * sigm(i1);
        c0 = cn0; c1 = cn1;

        float hv0 = sigm(o0) * tanh_(cn0);
        float hv1 = sigm(o1) * tanh_(cn1);

        // publish h_new for next step; stage out tile in smem
        *(float2*)&g_h[d][buf ^ 1][h][r0] = make_float2(hv0, hv1);
        ob[r0 * 8 + hl] = hv0;
        ob[(r0 + 1) * 8 + hl] = hv1;

        __syncthreads();                      // all stores executed, reads done
        if (tid == 0) st_release(myflag, (unsigned)(t + 1));

        // coalesced out write (overlaps next spin): out[s][b][d*512+hh0+0..7]
        if (tid < 128) {
            int b = tid >> 1, hseg = (tid & 1) * 4;
            float4 v = *(float4*)&ob[b * 8 + hseg];
            *(float4*)&out[(size_t)s * (Bsz * 2 * Hsz) + (size_t)b * (2 * Hsz)
                           + d * Hsz + hh0 + hseg] = v;
        }
    }
}

// ---------------------------------------------------------------------------
__global__ void k_gather(const unsigned char* __restrict__ mask,
                         const float* __restrict__ out,
                         float* __restrict__ hf, float* __restrict__ hb)
{
    __shared__ int sred[256];
    __shared__ int smode;
    const int b = blockIdx.x, tid = threadIdx.x;

    if (tid == 0) {
        const int* ip = (const int*)mask;
        int bytemode = 0;
        for (int j = 0; j < 8; j++) {
            unsigned int v = (unsigned int)ip[j];
            if (v > 1u) bytemode = 1;
        }
        smode = bytemode;
    }
    __syncthreads();

    int v;
    if (smode) {
        v  = mask[b * Ssz + tid] ? 1 : 0;
        v += mask[b * Ssz + 256 + tid] ? 1 : 0;
    } else {
        const int* ip = (const int*)mask;
        v  = ip[b * Ssz + tid] ? 1 : 0;
        v += ip[b * Ssz + 256 + tid] ? 1 : 0;
    }
    sred[tid] = v;
    __syncthreads();
    for (int st = 128; st > 0; st >>= 1) {
        if (tid < st) sred[tid] += sred[tid + st];
        __syncthreads();
    }
    int len = sred[0];
    int idx = len > 0 ? len - 1 : 0;

    hf[b * Hsz + tid]       = out[(size_t)idx * 65536 + b * 1024 + tid];
    hf[b * Hsz + tid + 256] = out[(size_t)idx * 65536 + b * 1024 + tid + 256];
    hb[b * Hsz + tid]       = out[(size_t)b * 1024 + 512 + tid];
    hb[b * Hsz + tid + 256] = out[(size_t)b * 1024 + 512 + tid + 256];
}

// ---------------------------------------------------------------------------
extern "C" void kernel_launch(void* const* d_in, const int* in_sizes, int n_in,
                              void* d_out, int out_size)
{
    const float* x  = (const float*)d_in[0];
    const unsigned char* mask = (const unsigned char*)d_in[1];
    const float* Uf = (const float*)d_in[2];
    const float* Wf = (const float*)d_in[3];
    const float* bf = (const float*)d_in[4];
    const float* Ub = (const float*)d_in[5];
    const float* Wb = (const float*)d_in[6];
    const float* bb = (const float*)d_in[7];

    float* out = (float*)d_out;                       // [S][B][2H]
    float* hf  = out + (size_t)Ssz * Bsz * 2 * Hsz;   // [B][H]
    float* hb  = hf + (size_t)Bsz * Hsz;              // [B][H]

    k_init<<<512, 256>>>();
    k_u2<<<2048, 256>>>(Uf, Ub);

    dim3 gx(64, 512);
    k_xw<<<gx, 256>>>(x, Wf, Wb, bf, bb);

    cudaFuncSetAttribute(k_rec, cudaFuncAttributeMaxDynamicSharedMemorySize, SM_REC);
    k_rec<<<128, 256, SM_REC>>>(out);

    k_gather<<<64, 256>>>(mask, out, hf, hb);
}

// round 10
// speedup vs baseline: 1.6596x; 1.0036x over previous
#include <cuda_runtime.h>

#define Bsz 64
#define Ssz 512
#define Hsz 512
#define Isz 512
#define KT  32

typedef unsigned long long u64;

// Scratch (allocation-free rule: __device__ globals)
__device__ float g_xw[134217728];         // [d][s][g][h][b] : 512MB
__device__ float g_h[2][2][Hsz][Bsz];     // [dir][buf][h(k)][b]
__device__ u64   g_U2[2][Hsz][Hsz][4];    // [dir][k][h][g] = {U,U} dup pairs, 16MB
__device__ unsigned g_flag[2][64];        // per-block step flags

__device__ __forceinline__ u64 packf2(float x, float y) {
    u64 r; asm("mov.b64 %0, {%1,%2};" : "=l"(r) : "f"(x), "f"(y)); return r;
}
__device__ __forceinline__ void unpack2(u64 v, float& x, float& y) {
    asm("mov.b64 {%0,%1}, %2;" : "=f"(x), "=f"(y) : "l"(v));
}
__device__ __forceinline__ void fma2(u64& d, u64 a, u64 b) {
    asm("fma.rn.f32x2 %0, %1, %2, %0;" : "+l"(d) : "l"(a), "l"(b));
}
__device__ __forceinline__ void add2(u64& d, u64 a) {
    asm("add.rn.f32x2 %0, %0, %1;" : "+l"(d) : "l"(a));
}
__device__ __forceinline__ float sigm(float x) {
    float e; asm("ex2.approx.f32 %0, %1;" : "=f"(e) : "f"(x * -1.4426950408889634f));
    float r; asm("rcp.approx.f32 %0, %1;" : "=f"(r) : "f"(1.0f + e));
    return r;
}
__device__ __forceinline__ float tanh_(float x) {
    float e; asm("ex2.approx.f32 %0, %1;" : "=f"(e) : "f"(x * 2.8853900817779268f));
    float r; asm("rcp.approx.f32 %0, %1;" : "=f"(r) : "f"(1.0f + e));
    return 1.0f - 2.0f * r;
}
__device__ __forceinline__ void st_release(unsigned* p, unsigned v) {
    asm volatile("st.release.gpu.global.u32 [%0], %1;" :: "l"(p), "r"(v) : "memory");
}
__device__ __forceinline__ unsigned ld_acquire(const unsigned* p) {
    unsigned v;
    asm volatile("ld.acquire.gpu.global.u32 %0, [%1];" : "=r"(v) : "l"(p) : "memory");
    return v;
}

// ---------------------------------------------------------------------------
__global__ void k_init() {
    int i = blockIdx.x * 256 + threadIdx.x;
    float* ph = &g_h[0][0][0][0];
    if (i < 2 * 2 * Hsz * Bsz) ph[i] = 0.0f;
    if (i < 128) (&g_flag[0][0])[i] = 0u;
}

// Build g_U2[d][k][h][g] = {U[d][g][k][h], same}.
__global__ void k_u2(const float* __restrict__ Uf, const float* __restrict__ Ub) {
    int i = blockIdx.x * 256 + threadIdx.x;       // over 2*512*512 (d,k,h)
    int d = i >> 18;
    int k = (i >> 9) & 511;
    int h = i & 511;
    const float* U = d ? Ub : Uf;
    #pragma unroll
    for (int g = 0; g < 4; g++) {
        float u = U[(size_t)g * (Hsz * Hsz) + (size_t)k * Hsz + h];
        g_U2[d][k][h][g] = packf2(u, u);
    }
}

// ---------------------------------------------------------------------------
// Input projection: xw[d][s][g][h][b] = sum_i x[b][s][i] * W_d[g][i][h] + b_d[g][h]
__global__ __launch_bounds__(256) void k_xw(
    const float* __restrict__ x,
    const float* __restrict__ Wf, const float* __restrict__ Wb,
    const float* __restrict__ bf, const float* __restrict__ bb)
{
    __shared__ float As[32][66];   // As[k][row(b)]
    __shared__ float Bs[32][68];   // Bs[k][col(h)]

    const int tid = threadIdx.x;
    const int s = blockIdx.y;
    const int ct = blockIdx.x;             // 0..63
    const int d = ct >> 5;
    const int g = (ct >> 3) & 3;
    const int h0 = (ct & 7) * 64;

    const float* W = (d ? Wb : Wf) + (size_t)g * Hsz * Isz + h0;
    const float* bias = (d ? bb : bf) + g * Hsz + h0;

    const int ra = tid >> 3, k4 = tid & 7;     // A staging
    const int c4 = tid & 15, kb = tid >> 4;    // B staging
    const float* xg = x + ((size_t)ra * Ssz + s) * Isz + k4 * 4;
    const size_t xrow2 = (size_t)32 * Ssz * Isz;

    const int l = tid & 31, w = tid >> 5;

    u64 acc[2][4] = {};

    float4 rA0 = *(const float4*)(xg);
    float4 rA1 = *(const float4*)(xg + xrow2);
    float4 rB0 = *(const float4*)(W + (size_t)kb * Hsz + c4 * 4);
    float4 rB1 = *(const float4*)(W + (size_t)(kb + 16) * Hsz + c4 * 4);

    for (int t = 0; t < 16; t++) {
        {
            int kk = k4 * 4;
            As[kk + 0][ra] = rA0.x; As[kk + 1][ra] = rA0.y;
            As[kk + 2][ra] = rA0.z; As[kk + 3][ra] = rA0.w;
            As[kk + 0][ra + 32] = rA1.x; As[kk + 1][ra + 32] = rA1.y;
            As[kk + 2][ra + 32] = rA1.z; As[kk + 3][ra + 32] = rA1.w;
            *(float4*)&Bs[kb][c4 * 4] = rB0;
            *(float4*)&Bs[kb + 16][c4 * 4] = rB1;
        }
        __syncthreads();
        if (t < 15) {
            int k0 = (t + 1) * 32;
            rA0 = *(const float4*)(xg + k0);
            rA1 = *(const float4*)(xg + xrow2 + k0);
            rB0 = *(const float4*)(W + (size_t)(k0 + kb) * Hsz + c4 * 4);
            rB1 = *(const float4*)(W + (size_t)(k0 + kb + 16) * Hsz + c4 * 4);
        }
        #pragma unroll
        for (int kk = 0; kk < 32; kk++) {
            float2 a = *(const float2*)&As[kk][2 * l];
            u64 a0 = packf2(a.x, a.x);
            u64 a1 = packf2(a.y, a.y);
            ulonglong2 b01 = *(const ulonglong2*)&Bs[kk][8 * w];
            ulonglong2 b23 = *(const ulonglong2*)&Bs[kk][8 * w + 4];
            fma2(acc[0][0], a0, b01.x); fma2(acc[0][1], a0, b01.y);
            fma2(acc[0][2], a0, b23.x); fma2(acc[0][3], a0, b23.y);
            fma2(acc[1][0], a1, b01.x); fma2(acc[1][1], a1, b01.y);
            fma2(acc[1][2], a1, b23.x); fma2(acc[1][3], a1, b23.y);
        }
        __syncthreads();
    }

    size_t gb = (((size_t)d * Ssz + s) * 4 + g) * (size_t)Hsz * Bsz;
    #pragma unroll
    for (int j = 0; j < 4; j++) {
        float2 bb2 = *(const float2*)&bias[8 * w + 2 * j];
        float p0, p1, q0, q1;
        unpack2(acc[0][j], p0, p1);
        unpack2(acc[1][j], q0, q1);
        int hc = h0 + 8 * w + 2 * j;
        *(float2*)&g_xw[gb + (size_t)hc * Bsz + 2 * l] =
            make_float2(p0 + bb2.x, q0 + bb2.x);
        *(float2*)&g_xw[gb + (size_t)(hc + 1) * Bsz + 2 * l] =
            make_float2(p1 + bb2.y, q1 + bb2.y);
    }
}

// ---------------------------------------------------------------------------
// Persistent recurrence kernel, split-K: 512 threads, half kh accumulates
// k in [kh*256, kh*256+256), then half 1's partials are reduced into half 0
// through smem and half 0 runs the pointwise cell.
// Grid 128 (d = bx>>6, 8-h slab), 1 block/SM.
// Dynamic smem: As[2][2][32][64] f32 32KB | Bs[512][8][4] u64 128KB |
//               red[256][4] u64 8KB | ob[64][8] f32 2KB   = 174KB
#define SM_AS   0
#define SM_BS   32768
#define SM_RED  (32768 + 131072)
#define SM_OB   (SM_RED + 8192)
#define SM_REC  (SM_OB + 2048)

__global__ __launch_bounds__(512, 1) void k_rec(float* __restrict__ out)
{
    extern __shared__ char smraw[];
    float* As  = (float*)(smraw + SM_AS);    // [kh][buf][32][64]
    u64*   Bs  = (u64*)  (smraw + SM_BS);    // [k][hl][g] = [512][8][4]
    u64*   red = (u64*)  (smraw + SM_RED);   // [256][4]
    float* ob  = (float*)(smraw + SM_OB);    // [64][8]

    const int tid = threadIdx.x;
    const int kh = tid >> 8;                 // k-half: 0 or 1
    const int t256 = tid & 255;
    const int d = blockIdx.x >> 6;
    const int blk = blockIdx.x & 63;
    const int hh0 = blk * 8;

    // ---- load U slab once (512 threads)
    {
        const u64* src = &g_U2[d][0][0][0];
        for (int i = tid; i < 16384; i += 512)
            Bs[i] = src[((size_t)(i >> 5)) * 2048 + hh0 * 4 + (i & 31)];
    }

    // compute indices (within half)
    const int l = t256 & 31, w = t256 >> 5;
    const int r0 = 16 * (w & 3) + 2 * (l & 7);
    const int hl = 4 * (w >> 2) + (l >> 3);
    const int h = hh0 + hl;

    // A staging indices (within half): k-row kA of this half's tile
    const int kA = t256 >> 3, segA = t256 & 7;
    const int kbase = kh * 256;              // this half's k offset

    unsigned* myflag = &g_flag[d][blk];
    const unsigned* flags = &g_flag[d][0];

    const float* xwd = &g_xw[0] + (size_t)d * Ssz * 4 * Hsz * Bsz
                     + (size_t)h * Bsz + r0;
    const u64* Bp = Bs + hl * 4;
    float* Ah = As + kh * (2 * 32 * 64);     // this half's double buffer

    float c0 = 0.0f, c1 = 0.0f;
    __syncthreads();   // U slab visible

    #pragma unroll 1
    for (int t = 0; t < Ssz; t++) {
        const int s = d ? (Ssz - 1 - t) : t;
        const int buf = t & 1;
        const float* hp = &g_h[d][buf][0][0] + (size_t)(kbase + kA) * Bsz + segA * 8;

        // half 0 seeds acc with xw (issued before wait -> overlaps spin)
        u64 acc[4] = {};
        if (kh == 0) {
            const float* xwp = xwd + (size_t)s * 4 * Hsz * Bsz;
            #pragma unroll
            for (int g = 0; g < 4; g++)
                acc[g] = *(const u64*)(xwp + (size_t)g * Hsz * Bsz);
        }

        // wait: all 64 blocks of this direction finished step t-1.
        if (t > 0) {
            if (tid < 64) {
                while (ld_acquire(flags + tid) < (unsigned)t) { }
            }
            __syncthreads();
        }

        // prologue: this half's A tile 0
        float4 a0 = *(const float4*)(hp);
        float4 a1 = *(const float4*)(hp + 4);
        *(float4*)&Ah[(0 * 32 + kA) * 64 + segA * 8] = a0;
        *(float4*)&Ah[(0 * 32 + kA) * 64 + segA * 8 + 4] = a1;
        __syncthreads();

        #pragma unroll 1
        for (int tt = 0; tt < 8; tt++) {
            const int sb = tt & 1;
            if (tt < 7) {
                const float* hn = hp + (size_t)(tt + 1) * (KT * Bsz);
                a0 = *(const float4*)(hn);
                a1 = *(const float4*)(hn + 4);
            }
            const float* Asb = Ah + sb * (32 * 64);
            const u64* Bt = Bp + (size_t)(kbase + tt * KT) * 32;
            #pragma unroll
            for (int kk = 0; kk < KT; kk++) {
                u64 a2 = *(const u64*)&Asb[kk * 64 + r0];
                ulonglong2 b01 = *(const ulonglong2*)(Bt + (size_t)kk * 32);
                ulonglong2 b23 = *(const ulonglong2*)(Bt + (size_t)kk * 32 + 2);
                fma2(acc[0], a2, b01.x);
                fma2(acc[1], a2, b01.y);
                fma2(acc[2], a2, b23.x);
                fma2(acc[3], a2, b23.y);
            }
            if (tt < 7) {
                const int nb = sb ^ 1;
                float* dst = Ah + nb * (32 * 64) + kA * 64 + segA * 8;
                *(float4*)(dst) = a0;
                *(float4*)(dst + 4) = a1;
                __syncthreads();
            }
        }

        // reduce half 1 partials into half 0
        if (kh == 1) {
            u64* rp = red + t256 * 4;
            rp[0] = acc[0]; rp[1] = acc[1]; rp[2] = acc[2]; rp[3] = acc[3];
        }
        __syncthreads();

        if (kh == 0) {
            const u64* rp = red + t256 * 4;
            add2(acc[0], rp[0]); add2(acc[1], rp[1]);
            add2(acc[2], rp[2]); add2(acc[3], rp[3]);

            // Pointwise LSTM cell (gate order: f, g, i, o)
            float f0, f1, gg0, gg1, i0, i1, o0, o1;
            unpack2(acc[0], f0, f1);
            unpack2(acc[1], gg0, gg1);
            unpack2(acc[2], i0, i1);
            unpack2(acc[3], o0, o1);

            float cn0 = c0 * sigm(f0) + tanh_(gg0) * sigm(i0);
            float cn1 = c1 * sigm(f1) + tanh_(gg1) * sigm(i1);
            c0 = cn0; c1 = cn1;

            float hv0 = sigm(o0) * tanh_(cn0);
            float hv1 = sigm(o1) * tanh_(cn1);

            // publish h_new for next step; stage out tile in smem
            *(float2*)&g_h[d][buf ^ 1][h][r0] = make_float2(hv0, hv1);
            ob[r0 * 8 + hl] = hv0;
            ob[(r0 + 1) * 8 + hl] = hv1;
        }

        __syncthreads();                      // h stores + ob complete, reads done
        if (tid == 0) st_release(myflag, (unsigned)(t + 1));

        // coalesced out write (overlaps next spin): out[s][b][d*512+hh0+0..7]
        if (tid < 128) {
            int b = tid >> 1, hseg = (tid & 1) * 4;
            float4 v = *(float4*)&ob[b * 8 + hseg];
            *(float4*)&out[(size_t)s * (Bsz * 2 * Hsz) + (size_t)b * (2 * Hsz)
                           + d * Hsz + hh0 + hseg] = v;
        }
    }
}

// ---------------------------------------------------------------------------
__global__ void k_gather(const unsigned char* __restrict__ mask,
                         const float* __restrict__ out,
                         float* __restrict__ hf, float* __restrict__ hb)
{
    __shared__ int sred[256];
    __shared__ int smode;
    const int b = blockIdx.x, tid = threadIdx.x;

    if (tid == 0) {
        const int* ip = (const int*)mask;
        int bytemode = 0;
        for (int j = 0; j < 8; j++) {
            unsigned int v = (unsigned int)ip[j];
            if (v > 1u) bytemode = 1;
        }
        smode = bytemode;
    }
    __syncthreads();

    int v;
    if (smode) {
        v  = mask[b * Ssz + tid] ? 1 : 0;
        v += mask[b * Ssz + 256 + tid] ? 1 : 0;
    } else {
        const int* ip = (const int*)mask;
        v  = ip[b * Ssz + tid] ? 1 : 0;
        v += ip[b * Ssz + 256 + tid] ? 1 : 0;
    }
    sred[tid] = v;
    __syncthreads();
    for (int st = 128; st > 0; st >>= 1) {
        if (tid < st) sred[tid] += sred[tid + st];
        __syncthreads();
    }
    int len = sred[0];
    int idx = len > 0 ? len - 1 : 0;

    hf[b * Hsz + tid]       = out[(size_t)idx * 65536 + b * 1024 + tid];
    hf[b * Hsz + tid + 256] = out[(size_t)idx * 65536 + b * 1024 + tid + 256];
    hb[b * Hsz + tid]       = out[(size_t)b * 1024 + 512 + tid];
    hb[b * Hsz + tid + 256] = out[(size_t)b * 1024 + 512 + tid + 256];
}

// ---------------------------------------------------------------------------
extern "C" void kernel_launch(void* const* d_in, const int* in_sizes, int n_in,
                              void* d_out, int out_size)
{
    const float* x  = (const float*)d_in[0];
    const unsigned char* mask = (const unsigned char*)d_in[1];
    const float* Uf = (const float*)d_in[2];
    const float* Wf = (const float*)d_in[3];
    const float* bf = (const float*)d_in[4];
    const float* Ub = (const float*)d_in[5];
    const float* Wb = (const float*)d_in[6];
    const float* bb = (const float*)d_in[7];

    float* out = (float*)d_out;                       // [S][B][2H]
    float* hf  = out + (size_t)Ssz * Bsz * 2 * Hsz;   // [B][H]
    float* hb  = hf + (size_t)Bsz * Hsz;              // [B][H]

    k_init<<<512, 256>>>();
    k_u2<<<2048, 256>>>(Uf, Ub);

    dim3 gx(64, 512);
    k_xw<<<gx, 256>>>(x, Wf, Wb, bf, bb);

    cudaFuncSetAttribute(k_rec, cudaFuncAttributeMaxDynamicSharedMemorySize, SM_REC);
    k_rec<<<128, 512, SM_REC>>>(out);

    k_gather<<<64, 256>>>(mask, out, hf, hb);
}